// round 2
// baseline (speedup 1.0000x reference)
#include <cuda_runtime.h>
#include <math.h>

// ---------------- problem constants ----------------
#define Bb   2
#define SS   2048
#define DD   1024
#define HH   16
#define HDIM 64
#define EE   4
#define KSEL 2
#define HIDD 4096
#define TT   (Bb*SS)   // 4096 tokens

// ---------------- scratch (device globals; no allocation allowed) -------------
static const size_t OFF_H     = 0;                                   // TT*DD
static const size_t OFF_QKV   = OFF_H     + (size_t)TT*DD;           // TT*3*DD
static const size_t OFF_ATTN  = OFF_QKV   + (size_t)TT*3*DD;         // TT*DD
static const size_t OFF_X1    = OFF_ATTN  + (size_t)TT*DD;           // TT*DD
static const size_t OFF_H2    = OFF_X1    + (size_t)TT*DD;           // TT*DD
static const size_t OFF_SUP   = OFF_H2    + (size_t)TT*DD;           // TT*HIDD
static const size_t OFF_SDOWN = OFF_SUP   + (size_t)TT*HIDD;         // TT*DD
static const size_t OFF_UP    = OFF_SDOWN + (size_t)TT*DD;           // EE*TT*HIDD
static const size_t OFF_EO    = OFF_UP    + (size_t)EE*TT*HIDD;      // EE*TT*DD
static const size_t OFF_PROBS = OFF_EO    + (size_t)EE*TT*DD;        // TT*EE
static const size_t OFF_TOPW  = OFF_PROBS + (size_t)TT*EE;           // TT*KSEL
static const size_t F_TOTAL   = OFF_TOPW  + (size_t)TT*KSEL;

__device__ float g_f[F_TOTAL];

static const size_t IOFF_SLOT    = 0;                       // EE*TT   slot -> token
static const size_t IOFF_TOKSLOT = IOFF_SLOT + EE*TT;       // TT*KSEL token -> slot
static const size_t IOFF_TOPI    = IOFF_TOKSLOT + TT*KSEL;  // TT*KSEL
static const size_t IOFF_CNT     = IOFF_TOPI + TT*KSEL;     // EE
__device__ int g_i[IOFF_CNT + EE];

// ---------------- helpers ----------------
__device__ __forceinline__ float gelu_tanh(float x) {
    float z = 0.7978845608028654f * (x + 0.044715f * x * x * x);
    float e = __expf(2.f * z);
    float th = 1.f - 2.f / (e + 1.f);
    return 0.5f * x * (1.f + th);
}

// ---------------- LayerNorm: one block per token ----------------
__global__ void ln_kernel(const float* __restrict__ x, const float* __restrict__ g,
                          const float* __restrict__ b, float* __restrict__ out) {
    int t = blockIdx.x, tid = threadIdx.x;
    const float* xr = x + (size_t)t * DD;
    float v[4], s = 0.f, sq = 0.f;
#pragma unroll
    for (int k = 0; k < 4; k++) {
        v[k] = xr[tid + k * 256];
        s += v[k]; sq += v[k] * v[k];
    }
    __shared__ float rs[256], rq[256];
    rs[tid] = s; rq[tid] = sq;
    __syncthreads();
    for (int o = 128; o > 0; o >>= 1) {
        if (tid < o) { rs[tid] += rs[tid + o]; rq[tid] += rq[tid + o]; }
        __syncthreads();
    }
    float mean = rs[0] * (1.f / DD);
    float var  = rq[0] * (1.f / DD) - mean * mean;
    float inv  = rsqrtf(var + 1e-5f);
    float* orow = out + (size_t)t * DD;
#pragma unroll
    for (int k = 0; k < 4; k++) {
        int d = tid + k * 256;
        orow[d] = (v[k] - mean) * inv * g[d] + b[d];
    }
}

// ---------------- generic NT SGEMM: C[M,N] = A[M,K] * Bw[N,K]^T + bias ---------
// EPI: 0 = none, 1 = gelu, 2 = + resid
template <int EPI>
__global__ void __launch_bounds__(256) sgemm_nt(
    const float* __restrict__ A, const float* __restrict__ Bw,
    const float* __restrict__ bias, const float* __restrict__ resid,
    float* __restrict__ C, int M, int N, int Kd,
    const int* __restrict__ rowIdx, const int* __restrict__ cnt,
    size_t aZ, size_t bZ, size_t biasZ, size_t cZ, size_t idxZ) {
    int z = blockIdx.z;
    A += (size_t)z * aZ; Bw += (size_t)z * bZ;
    bias += (size_t)z * biasZ; C += (size_t)z * cZ;
    if (rowIdx) rowIdx += (size_t)z * idxZ;
    if (cnt) M = cnt[z];
    int mBase = blockIdx.y * 128;
    if (mBase >= M) return;
    int n0 = blockIdx.x * 128;
    int tid = threadIdx.x;
    int tx = tid & 15, ty = tid >> 4;
    int loadRow = tid >> 1;
    int loadK4  = (tid & 1) * 4;

    __shared__ float As[8][132];
    __shared__ float Bs[8][132];

    int gm = mBase + loadRow;
    bool rowOK = gm < M;
    const float* aPtr = A;
    if (rowOK) {
        int sr = rowIdx ? rowIdx[gm] : gm;
        aPtr = A + (size_t)sr * Kd + loadK4;
    }
    const float* bPtr = Bw + (size_t)(n0 + loadRow) * Kd + loadK4;

    float acc[8][8];
#pragma unroll
    for (int i = 0; i < 8; i++)
#pragma unroll
        for (int j = 0; j < 8; j++) acc[i][j] = 0.f;

    for (int k0 = 0; k0 < Kd; k0 += 8) {
        float4 av = rowOK ? *(const float4*)(aPtr + k0) : make_float4(0, 0, 0, 0);
        float4 bv = *(const float4*)(bPtr + k0);
        __syncthreads();
        As[loadK4 + 0][loadRow] = av.x; As[loadK4 + 1][loadRow] = av.y;
        As[loadK4 + 2][loadRow] = av.z; As[loadK4 + 3][loadRow] = av.w;
        Bs[loadK4 + 0][loadRow] = bv.x; Bs[loadK4 + 1][loadRow] = bv.y;
        Bs[loadK4 + 2][loadRow] = bv.z; Bs[loadK4 + 3][loadRow] = bv.w;
        __syncthreads();
#pragma unroll
        for (int kk = 0; kk < 8; kk++) {
            float4 a0 = *(const float4*)&As[kk][ty * 8];
            float4 a1 = *(const float4*)&As[kk][ty * 8 + 4];
            float4 b0 = *(const float4*)&Bs[kk][tx * 8];
            float4 b1 = *(const float4*)&Bs[kk][tx * 8 + 4];
            float a[8] = {a0.x, a0.y, a0.z, a0.w, a1.x, a1.y, a1.z, a1.w};
            float bb[8] = {b0.x, b0.y, b0.z, b0.w, b1.x, b1.y, b1.z, b1.w};
#pragma unroll
            for (int i = 0; i < 8; i++)
#pragma unroll
                for (int j = 0; j < 8; j++) acc[i][j] += a[i] * bb[j];
        }
    }

#pragma unroll
    for (int i = 0; i < 8; i++) {
        int r = mBase + ty * 8 + i;
        if (r >= M) continue;
        float* crow = C + (size_t)r * N + n0 + tx * 8;
        const float* brow = bias + n0 + tx * 8;
        const float* rrow = (EPI == 2) ? (resid + (size_t)r * N + n0 + tx * 8) : nullptr;
        float o[8];
#pragma unroll
        for (int j = 0; j < 8; j++) {
            float v = acc[i][j] + brow[j];
            if (EPI == 1) v = gelu_tanh(v);
            if (EPI == 2) v += rrow[j];
            o[j] = v;
        }
        *(float4*)crow       = make_float4(o[0], o[1], o[2], o[3]);
        *(float4*)(crow + 4) = make_float4(o[4], o[5], o[6], o[7]);
    }
}

// ---------------- causal flash attention -------------------------------------
__global__ void __launch_bounds__(512) attn_kernel(const float* __restrict__ qkv,
                                                   float* __restrict__ out) {
    __shared__ float q_s[16][64];
    __shared__ float k_s[32][65];
    __shared__ float v_s[32][64];
    int bh = blockIdx.y;
    int b = bh >> 4, h = bh & 15;
    int q0 = blockIdx.x * 16;
    int tid = threadIdx.x;
    int w = tid >> 5, lane = tid & 31;

    {   // load 16 queries (scaled by 1/sqrt(64))
        int i = tid * 2;
        int qi = i >> 6, d = i & 63;
        const float* src = qkv + ((size_t)(b * SS + q0 + qi)) * (3 * DD) + h * 64 + d;
        float2 v = *(const float2*)src;
        q_s[qi][d]     = v.x * 0.125f;
        q_s[qi][d + 1] = v.y * 0.125f;
    }
    __syncthreads();
    float qr[64];
#pragma unroll
    for (int d = 0; d < 64; d++) qr[d] = q_s[w][d];

    int q = q0 + w;
    float M = -1e30f, L = 0.f, o0 = 0.f, o1 = 0.f;
    int nkeys = q0 + 16;

    for (int t0 = 0; t0 < nkeys; t0 += 32) {
        __syncthreads();
        {   // cooperative K/V tile load (32x64 each)
            int r  = tid >> 4;
            int c4 = (tid & 15) * 4;
            int key = t0 + r;
            float4 kv = make_float4(0, 0, 0, 0), vv = make_float4(0, 0, 0, 0);
            if (key < SS) {
                size_t base = ((size_t)(b * SS + key)) * (3 * DD) + h * 64 + c4;
                kv = *(const float4*)(qkv + DD + base);
                vv = *(const float4*)(qkv + 2 * DD + base);
            }
            k_s[r][c4 + 0] = kv.x; k_s[r][c4 + 1] = kv.y;
            k_s[r][c4 + 2] = kv.z; k_s[r][c4 + 3] = kv.w;
            *(float4*)&v_s[r][c4] = vv;
        }
        __syncthreads();

        int key = t0 + lane;
        bool act = (key <= q);
        float s = -1e30f;
        if (act) {
            float a = 0.f;
#pragma unroll
            for (int d = 0; d < 64; d++) a += qr[d] * k_s[lane][d];
            s = a;
        }
        float mcur = s;
#pragma unroll
        for (int off = 16; off > 0; off >>= 1)
            mcur = fmaxf(mcur, __shfl_xor_sync(0xffffffffu, mcur, off));
        if (mcur > M) {
            float sc = __expf(M - mcur);
            o0 *= sc; o1 *= sc; L *= sc;
            M = mcur;
        }
        float p = act ? __expf(s - M) : 0.f;
        float ls = p;
#pragma unroll
        for (int off = 16; off > 0; off >>= 1)
            ls += __shfl_xor_sync(0xffffffffu, ls, off);
        L += ls;
#pragma unroll
        for (int j = 0; j < 32; j++) {
            float pj = __shfl_sync(0xffffffffu, p, j);
            float2 vv = *(const float2*)&v_s[j][lane * 2];
            o0 += pj * vv.x;
            o1 += pj * vv.y;
        }
    }
    float inv = 1.f / L;
    float2 res; res.x = o0 * inv; res.y = o1 * inv;
    *(float2*)(out + ((size_t)(b * SS + q)) * DD + h * 64 + lane * 2) = res;
}

// ---------------- MoE router ----------------
__global__ void router_kernel(const float* __restrict__ h2, const float* __restrict__ Wg,
                              float* __restrict__ probs, float* __restrict__ topw,
                              int* __restrict__ topi, int* __restrict__ slot_tok,
                              int* __restrict__ tok_slot, int* __restrict__ cnt) {
    int t = blockIdx.x, tid = threadIdx.x;  // 128 threads
    const float* hr = h2 + (size_t)t * DD;
    float a0 = 0, a1 = 0, a2 = 0, a3 = 0;
    for (int d = tid; d < DD; d += 128) {
        float hv = hr[d];
        a0 += hv * Wg[d];
        a1 += hv * Wg[DD + d];
        a2 += hv * Wg[2 * DD + d];
        a3 += hv * Wg[3 * DD + d];
    }
    __shared__ float r[4][128];
    r[0][tid] = a0; r[1][tid] = a1; r[2][tid] = a2; r[3][tid] = a3;
    __syncthreads();
    for (int o = 64; o > 0; o >>= 1) {
        if (tid < o) {
#pragma unroll
            for (int e = 0; e < 4; e++) r[e][tid] += r[e][tid + o];
        }
        __syncthreads();
    }
    if (tid == 0) {
        float l[4] = {r[0][0], r[1][0], r[2][0], r[3][0]};
        float m = fmaxf(fmaxf(l[0], l[1]), fmaxf(l[2], l[3]));
        float p[4], sum = 0.f;
#pragma unroll
        for (int e = 0; e < 4; e++) { p[e] = __expf(l[e] - m); sum += p[e]; }
#pragma unroll
        for (int e = 0; e < 4; e++) { p[e] /= sum; probs[t * 4 + e] = p[e]; }
        int i0 = 0;
#pragma unroll
        for (int e = 1; e < 4; e++) if (p[e] > p[i0]) i0 = e;
        int i1 = -1;
#pragma unroll
        for (int e = 0; e < 4; e++)
            if (e != i0 && (i1 < 0 || p[e] > p[i1])) i1 = e;
        float w0 = p[i0], w1 = p[i1], ws = w0 + w1;
        w0 /= ws; w1 /= ws;
        int pos0 = atomicAdd(&cnt[i0], 1);
        slot_tok[i0 * TT + pos0] = t;
        tok_slot[t * 2]     = i0 * TT + pos0;
        int pos1 = atomicAdd(&cnt[i1], 1);
        slot_tok[i1 * TT + pos1] = t;
        tok_slot[t * 2 + 1] = i1 * TT + pos1;
        topw[t * 2] = w0; topw[t * 2 + 1] = w1;
        topi[t * 2] = i0; topi[t * 2 + 1] = i1;
    }
}

// ---------------- aux loss ----------------
__global__ void aux_kernel(const float* __restrict__ probs, const int* __restrict__ topi,
                           float* __restrict__ auxout) {
    int tid = threadIdx.x;  // 512
    float ps[4] = {0, 0, 0, 0};
    float cs[4] = {0, 0, 0, 0};
    for (int t = tid; t < TT; t += 512) {
#pragma unroll
        for (int e = 0; e < 4; e++) ps[e] += probs[t * 4 + e];
        cs[topi[t * 2]] += 1.f;
        cs[topi[t * 2 + 1]] += 1.f;
    }
    __shared__ float sp[4][512], sc[4][512];
#pragma unroll
    for (int e = 0; e < 4; e++) { sp[e][tid] = ps[e]; sc[e][tid] = cs[e]; }
    __syncthreads();
    for (int o = 256; o > 0; o >>= 1) {
        if (tid < o) {
#pragma unroll
            for (int e = 0; e < 4; e++) {
                sp[e][tid] += sp[e][tid + o];
                sc[e][tid] += sc[e][tid + o];
            }
        }
        __syncthreads();
    }
    if (tid == 0) {
        float aux = 0.f;
#pragma unroll
        for (int e = 0; e < 4; e++) {
            float fi = sc[e][0] / (float)(TT * KSEL);
            float Pi = sp[e][0] / (float)TT;
            aux += fi * Pi;
        }
        auxout[0] = 0.01f * (float)EE * aux;
    }
}

// ---------------- final combine (SCALAR stores: xout may be 4B-aligned only) --
__global__ void combine_kernel(const float* __restrict__ x1, const float* __restrict__ sdown,
                               const float* __restrict__ eo, const float* __restrict__ topw,
                               const int* __restrict__ tok_slot, float* __restrict__ xout) {
    int t = blockIdx.x, tid = threadIdx.x;
    int c = tid * 4;
    int s0 = tok_slot[t * 2], s1 = tok_slot[t * 2 + 1];
    float w0 = topw[t * 2], w1 = topw[t * 2 + 1];
    float4 a  = *(const float4*)(x1 + (size_t)t * DD + c);
    float4 sd = *(const float4*)(sdown + (size_t)t * DD + c);
    float4 e0 = *(const float4*)(eo + (size_t)s0 * DD + c);
    float4 e1 = *(const float4*)(eo + (size_t)s1 * DD + c);
    float* o = xout + (size_t)t * DD + c;
    o[0] = a.x + sd.x + w0 * e0.x + w1 * e1.x;
    o[1] = a.y + sd.y + w0 * e0.y + w1 * e1.y;
    o[2] = a.z + sd.z + w0 * e0.z + w1 * e1.z;
    o[3] = a.w + sd.w + w0 * e0.w + w1 * e1.w;
}

// ---------------- launch ------------------------------------------------------
extern "C" void kernel_launch(void* const* d_in, const int* in_sizes, int n_in,
                              void* d_out, int out_size) {
    const float* x      = (const float*)d_in[0];
    const float* ln1_g  = (const float*)d_in[1];
    const float* ln1_b  = (const float*)d_in[2];
    const float* Wqkv   = (const float*)d_in[3];
    const float* bqkv   = (const float*)d_in[4];
    const float* Wo     = (const float*)d_in[5];
    const float* bo     = (const float*)d_in[6];
    const float* ln2_g  = (const float*)d_in[7];
    const float* ln2_b  = (const float*)d_in[8];
    const float* Wg     = (const float*)d_in[9];
    const float* We_up  = (const float*)d_in[10];
    const float* be_up  = (const float*)d_in[11];
    const float* We_dn  = (const float*)d_in[12];
    const float* be_dn  = (const float*)d_in[13];
    const float* Ws_up  = (const float*)d_in[14];
    const float* bs_up  = (const float*)d_in[15];
    const float* Ws_dn  = (const float*)d_in[16];
    const float* bs_dn  = (const float*)d_in[17];

    float* F = nullptr; int* I = nullptr;
    cudaGetSymbolAddress((void**)&F, g_f);
    cudaGetSymbolAddress((void**)&I, g_i);

    float* h     = F + OFF_H;
    float* qkv   = F + OFF_QKV;
    float* attn  = F + OFF_ATTN;
    float* x1    = F + OFF_X1;
    float* h2    = F + OFF_H2;
    float* sup   = F + OFF_SUP;
    float* sdown = F + OFF_SDOWN;
    float* upb   = F + OFF_UP;
    float* eob   = F + OFF_EO;
    float* probs = F + OFF_PROBS;
    float* topw  = F + OFF_TOPW;
    int* slot_tok = I + IOFF_SLOT;
    int* tok_slot = I + IOFF_TOKSLOT;
    int* topi     = I + IOFF_TOPI;
    int* cnt      = I + IOFF_CNT;

    float* outp = (float*)d_out;
    float* auxp = nullptr;
    float* xout = outp;
    if (out_size == TT * DD + 1) { auxp = outp; xout = outp + 1; }

    cudaMemsetAsync(cnt, 0, EE * sizeof(int));

    // 1) LN1
    ln_kernel<<<TT, 256>>>(x, ln1_g, ln1_b, h);
    // 2) QKV projection
    sgemm_nt<0><<<dim3(24, 32, 1), 256>>>(h, Wqkv, bqkv, nullptr, qkv,
                                          TT, 3 * DD, DD, nullptr, nullptr, 0, 0, 0, 0, 0);
    // 3) causal attention
    attn_kernel<<<dim3(SS / 16, Bb * HH), 512>>>(qkv, attn);
    // 4) output proj + residual
    sgemm_nt<2><<<dim3(8, 32, 1), 256>>>(attn, Wo, bo, x, x1,
                                         TT, DD, DD, nullptr, nullptr, 0, 0, 0, 0, 0);
    // 5) LN2
    ln_kernel<<<TT, 256>>>(x1, ln2_g, ln2_b, h2);
    // 6) router
    router_kernel<<<TT, 128>>>(h2, Wg, probs, topw, topi, slot_tok, tok_slot, cnt);
    // 7) aux loss
    if (auxp) aux_kernel<<<1, 512>>>(probs, topi, auxp);
    // 8) expert up (gathered, gelu), z = expert
    sgemm_nt<1><<<dim3(32, 32, 4), 256>>>(h2, We_up, be_up, nullptr, upb,
                                          TT, HIDD, DD, slot_tok, cnt,
                                          0, (size_t)HIDD * DD, (size_t)HIDD,
                                          (size_t)TT * HIDD, (size_t)TT);
    // 9) expert down
    sgemm_nt<0><<<dim3(8, 32, 4), 256>>>(upb, We_dn, be_dn, nullptr, eob,
                                         TT, DD, HIDD, nullptr, cnt,
                                         (size_t)TT * HIDD, (size_t)DD * HIDD, (size_t)DD,
                                         (size_t)TT * DD, 0);
    // 10) shared expert up (gelu)
    sgemm_nt<1><<<dim3(32, 32, 1), 256>>>(h2, Ws_up, bs_up, nullptr, sup,
                                          TT, HIDD, DD, nullptr, nullptr, 0, 0, 0, 0, 0);
    // 11) shared expert down
    sgemm_nt<0><<<dim3(8, 32, 1), 256>>>(sup, Ws_dn, bs_dn, nullptr, sdown,
                                         TT, DD, HIDD, nullptr, nullptr, 0, 0, 0, 0, 0);
    // 12) combine
    combine_kernel<<<TT, 256>>>(x1, sdown, eob, topw, tok_slot, xout);
}

// round 4
// speedup vs baseline: 1.8614x; 1.8614x over previous
#include <cuda_runtime.h>
#include <cuda_bf16.h>
#include <math.h>
#include <stdint.h>

// ---------------- problem constants ----------------
#define Bb   2
#define SS   2048
#define DD   1024
#define HH   16
#define HDIM 64
#define EE   4
#define KSEL 2
#define HIDD 4096
#define TT   (Bb*SS)   // 4096 tokens

// ---------------- scratch ----------------
static const size_t OFF_H     = 0;                                   // TT*DD
static const size_t OFF_QKV   = OFF_H     + (size_t)TT*DD;           // TT*3*DD
static const size_t OFF_ATTN  = OFF_QKV   + (size_t)TT*3*DD;         // TT*DD
static const size_t OFF_X1    = OFF_ATTN  + (size_t)TT*DD;           // TT*DD
static const size_t OFF_H2    = OFF_X1    + (size_t)TT*DD;           // TT*DD
static const size_t OFF_SUP   = OFF_H2    + (size_t)TT*DD;           // TT*HIDD
static const size_t OFF_SDOWN = OFF_SUP   + (size_t)TT*HIDD;         // TT*DD
static const size_t OFF_UP    = OFF_SDOWN + (size_t)TT*DD;           // EE*TT*HIDD
static const size_t OFF_EO    = OFF_UP    + (size_t)EE*TT*HIDD;      // EE*TT*DD
static const size_t OFF_PROBS = OFF_EO    + (size_t)EE*TT*DD;        // TT*EE
static const size_t OFF_TOPW  = OFF_PROBS + (size_t)TT*EE;           // TT*KSEL
static const size_t F_TOTAL   = OFF_TOPW  + (size_t)TT*KSEL;

__device__ float g_f[F_TOTAL];

static const size_t IOFF_SLOT    = 0;                       // EE*TT
static const size_t IOFF_TOKSLOT = IOFF_SLOT + EE*TT;       // TT*KSEL
static const size_t IOFF_TOPI    = IOFF_TOKSLOT + TT*KSEL;  // TT*KSEL
static const size_t IOFF_CNT     = IOFF_TOPI + TT*KSEL;     // EE
__device__ int g_i[IOFF_CNT + EE];

// ---------------- helpers ----------------
__device__ __forceinline__ float gelu_tanh(float x) {
    float z = 0.7978845608028654f * (x + 0.044715f * x * x * x);
    float e = __expf(2.f * z);
    float th = 1.f - 2.f / (e + 1.f);
    return 0.5f * x * (1.f + th);
}

__device__ __forceinline__ void mma_bf16(float* d, const uint32_t* a, const uint32_t* b) {
    asm volatile(
        "mma.sync.aligned.m16n8k16.row.col.f32.bf16.bf16.f32 "
        "{%0,%1,%2,%3}, {%4,%5,%6,%7}, {%8,%9}, {%0,%1,%2,%3};\n"
        : "+f"(d[0]), "+f"(d[1]), "+f"(d[2]), "+f"(d[3])
        : "r"(a[0]), "r"(a[1]), "r"(a[2]), "r"(a[3]), "r"(b[0]), "r"(b[1]));
}

__device__ __forceinline__ void ldsm4(uint32_t* r, uint32_t addr) {
    asm volatile("ldmatrix.sync.aligned.m8n8.x4.shared.b16 {%0,%1,%2,%3}, [%4];"
                 : "=r"(r[0]), "=r"(r[1]), "=r"(r[2]), "=r"(r[3]) : "r"(addr));
}

// split a float into bf16 hi + bf16 lo  (x ~= hi + lo, |err| ~ 2^-17 |x|)
__device__ __forceinline__ void split2(float x, float y, uint32_t& hi, uint32_t& lo) {
    __nv_bfloat16 hx = __float2bfloat16_rn(x);
    __nv_bfloat16 hy = __float2bfloat16_rn(y);
    __nv_bfloat16 lx = __float2bfloat16_rn(x - __bfloat162float(hx));
    __nv_bfloat16 ly = __float2bfloat16_rn(y - __bfloat162float(hy));
    __nv_bfloat162 h2 = __nv_bfloat162(hx, hy);
    __nv_bfloat162 l2 = __nv_bfloat162(lx, ly);
    hi = *reinterpret_cast<uint32_t*>(&h2);
    lo = *reinterpret_cast<uint32_t*>(&l2);
}

// ---------------- LayerNorm ----------------
__global__ void ln_kernel(const float* __restrict__ x, const float* __restrict__ g,
                          const float* __restrict__ b, float* __restrict__ out) {
    int t = blockIdx.x, tid = threadIdx.x;
    const float* xr = x + (size_t)t * DD;
    float v[4], s = 0.f, sq = 0.f;
#pragma unroll
    for (int k = 0; k < 4; k++) {
        v[k] = xr[tid + k * 256];
        s += v[k]; sq += v[k] * v[k];
    }
    __shared__ float rs[256], rq[256];
    rs[tid] = s; rq[tid] = sq;
    __syncthreads();
    for (int o = 128; o > 0; o >>= 1) {
        if (tid < o) { rs[tid] += rs[tid + o]; rq[tid] += rq[tid + o]; }
        __syncthreads();
    }
    float mean = rs[0] * (1.f / DD);
    float var  = rq[0] * (1.f / DD) - mean * mean;
    float inv  = rsqrtf(var + 1e-5f);
    float* orow = out + (size_t)t * DD;
#pragma unroll
    for (int k = 0; k < 4; k++) {
        int d = tid + k * 256;
        orow[d] = (v[k] - mean) * inv * g[d] + b[d];
    }
}

// ---------------- tensor-core NT GEMM: C[M,N] = A[M,K]*Bw[N,K]^T + bias -------
// bf16 split (hi+lo), 3-pass mma accumulation in fp32.
// Block 128x128, 8 warps of 64x32, k-tile 32.
// EPI: 0 none, 1 gelu, 2 +resid
#define LDAH 40   // smem row pitch in halves (32 data + 8 pad); 80B, 16B-aligned
template <int EPI>
__global__ void __launch_bounds__(256) hgemm_nt(
    const float* __restrict__ A, const float* __restrict__ Bw,
    const float* __restrict__ bias, const float* __restrict__ resid,
    float* __restrict__ C, int M, int N, int Kd,
    const int* __restrict__ rowIdx, const int* __restrict__ cnt,
    size_t aZ, size_t bZ, size_t biasZ, size_t cZ, size_t idxZ) {
    int z = blockIdx.z;
    A += (size_t)z * aZ; Bw += (size_t)z * bZ;
    bias += (size_t)z * biasZ; C += (size_t)z * cZ;
    if (rowIdx) rowIdx += (size_t)z * idxZ;
    if (cnt) M = cnt[z];
    int mBase = blockIdx.y * 128;
    if (mBase >= M) return;
    int n0 = blockIdx.x * 128;

    __shared__ __align__(16) uint16_t sAhi[128 * LDAH];
    __shared__ __align__(16) uint16_t sAlo[128 * LDAH];
    __shared__ __align__(16) uint16_t sBhi[128 * LDAH];
    __shared__ __align__(16) uint16_t sBlo[128 * LDAH];

    int tid = threadIdx.x;
    int wid = tid >> 5, lane = tid & 31;
    int warp_m = (wid >> 2) * 64;   // 0 or 64
    int warp_n = (wid & 3) * 32;    // 0,32,64,96

    // ---- gmem load mapping: thread -> (row, 16 contiguous k) ----
    int lr = tid >> 1;             // 0..127
    int lk = (tid & 1) * 16;       // 0 or 16 (float index within 32-wide k-tile)
    int gm = mBase + lr;
    bool rowOK = gm < M;
    const float* aPtr = A;
    if (rowOK) {
        int sr = rowIdx ? rowIdx[gm] : gm;
        aPtr = A + (size_t)sr * Kd + lk;
    }
    const float* bPtr = Bw + (size_t)(n0 + lr) * Kd + lk;

    char* sAhiW = (char*)sAhi + lr * (LDAH * 2) + lk * 2;
    char* sAloW = (char*)sAlo + lr * (LDAH * 2) + lk * 2;
    char* sBhiW = (char*)sBhi + lr * (LDAH * 2) + lk * 2;
    char* sBloW = (char*)sBlo + lr * (LDAH * 2) + lk * 2;

    // ---- ldmatrix addresses ----
    uint32_t aHiB = (uint32_t)__cvta_generic_to_shared(sAhi);
    uint32_t aLoB = (uint32_t)__cvta_generic_to_shared(sAlo);
    uint32_t bHiB = (uint32_t)__cvta_generic_to_shared(sBhi);
    uint32_t bLoB = (uint32_t)__cvta_generic_to_shared(sBlo);
    uint32_t aOff[4];
#pragma unroll
    for (int mt = 0; mt < 4; mt++) {
        int row = warp_m + mt * 16 + (lane & 15);
        int colh = (lane >> 4) * 8;
        aOff[mt] = (uint32_t)(row * LDAH + colh) * 2;
    }
    uint32_t bOff[2];
#pragma unroll
    for (int np = 0; np < 2; np++) {
        int row = warp_n + np * 16 + (lane & 7) + ((lane >> 4) << 3);
        int colh = ((lane >> 3) & 1) * 8;
        bOff[np] = (uint32_t)(row * LDAH + colh) * 2;
    }

    float c[4][4][4];
#pragma unroll
    for (int i = 0; i < 4; i++)
#pragma unroll
        for (int j = 0; j < 4; j++)
#pragma unroll
            for (int k = 0; k < 4; k++) c[i][j][k] = 0.f;

    for (int k0g = 0; k0g < Kd; k0g += 32) {
        float4 av[4], bv[4];
#pragma unroll
        for (int i = 0; i < 4; i++) {
            av[i] = rowOK ? *(const float4*)(aPtr + k0g + i * 4) : make_float4(0, 0, 0, 0);
            bv[i] = *(const float4*)(bPtr + k0g + i * 4);
        }
        __syncthreads();   // previous iter done reading smem
#pragma unroll
        for (int i = 0; i < 4; i++) {
            uint2 h, l;
            split2(av[i].x, av[i].y, h.x, l.x);
            split2(av[i].z, av[i].w, h.y, l.y);
            *(uint2*)(sAhiW + i * 8) = h;     // 4 floats -> 4 halves = 8 bytes
            *(uint2*)(sAloW + i * 8) = l;
            split2(bv[i].x, bv[i].y, h.x, l.x);
            split2(bv[i].z, bv[i].w, h.y, l.y);
            *(uint2*)(sBhiW + i * 8) = h;
            *(uint2*)(sBloW + i * 8) = l;
        }
        __syncthreads();

#pragma unroll
        for (int ks = 0; ks < 2; ks++) {
            uint32_t kb = ks * 32;   // 16 halves = 32 bytes
            uint32_t ah[4][4], al[4][4], bh[4][2], bl[4][2];
#pragma unroll
            for (int mt = 0; mt < 4; mt++) {
                ldsm4(ah[mt], aHiB + aOff[mt] + kb);
                ldsm4(al[mt], aLoB + aOff[mt] + kb);
            }
#pragma unroll
            for (int np = 0; np < 2; np++) {
                uint32_t r[4];
                ldsm4(r, bHiB + bOff[np] + kb);
                bh[2 * np][0] = r[0]; bh[2 * np][1] = r[1];
                bh[2 * np + 1][0] = r[2]; bh[2 * np + 1][1] = r[3];
                ldsm4(r, bLoB + bOff[np] + kb);
                bl[2 * np][0] = r[0]; bl[2 * np][1] = r[1];
                bl[2 * np + 1][0] = r[2]; bl[2 * np + 1][1] = r[3];
            }
#pragma unroll
            for (int mt = 0; mt < 4; mt++)
#pragma unroll
                for (int nt = 0; nt < 4; nt++) {
                    mma_bf16(c[mt][nt], ah[mt], bh[nt]);
                    mma_bf16(c[mt][nt], ah[mt], bl[nt]);
                    mma_bf16(c[mt][nt], al[mt], bh[nt]);
                }
        }
    }

    // ---- epilogue ----
#pragma unroll
    for (int mt = 0; mt < 4; mt++) {
#pragma unroll
        for (int nt = 0; nt < 4; nt++) {
            int col = n0 + warp_n + nt * 8 + (lane & 3) * 2;
            float2 bb = *(const float2*)(bias + col);
#pragma unroll
            for (int half = 0; half < 2; half++) {
                int r = mBase + warp_m + mt * 16 + (lane >> 2) + half * 8;
                if (r >= M) continue;
                float v0 = c[mt][nt][half * 2 + 0] + bb.x;
                float v1 = c[mt][nt][half * 2 + 1] + bb.y;
                if (EPI == 1) { v0 = gelu_tanh(v0); v1 = gelu_tanh(v1); }
                if (EPI == 2) {
                    float2 rr = *(const float2*)(resid + (size_t)r * N + col);
                    v0 += rr.x; v1 += rr.y;
                }
                *(float2*)(C + (size_t)r * N + col) = make_float2(v0, v1);
            }
        }
    }
}

// ---------------- causal flash attention -------------------------------------
__global__ void __launch_bounds__(512) attn_kernel(const float* __restrict__ qkv,
                                                   float* __restrict__ out) {
    __shared__ float q_s[16][64];
    __shared__ float k_s[32][65];
    __shared__ float v_s[32][64];
    int bh = blockIdx.y;
    int b = bh >> 4, h = bh & 15;
    int q0 = blockIdx.x * 16;
    int tid = threadIdx.x;
    int w = tid >> 5, lane = tid & 31;

    {
        int i = tid * 2;
        int qi = i >> 6, d = i & 63;
        const float* src = qkv + ((size_t)(b * SS + q0 + qi)) * (3 * DD) + h * 64 + d;
        float2 v = *(const float2*)src;
        q_s[qi][d]     = v.x * 0.125f;
        q_s[qi][d + 1] = v.y * 0.125f;
    }
    __syncthreads();
    float qr[64];
#pragma unroll
    for (int d = 0; d < 64; d++) qr[d] = q_s[w][d];

    int q = q0 + w;
    float M = -1e30f, L = 0.f, o0 = 0.f, o1 = 0.f;
    int nkeys = q0 + 16;

    for (int t0 = 0; t0 < nkeys; t0 += 32) {
        __syncthreads();
        {
            int r  = tid >> 4;
            int c4 = (tid & 15) * 4;
            int key = t0 + r;
            float4 kv = make_float4(0, 0, 0, 0), vv = make_float4(0, 0, 0, 0);
            if (key < SS) {
                size_t base = ((size_t)(b * SS + key)) * (3 * DD) + h * 64 + c4;
                kv = *(const float4*)(qkv + DD + base);
                vv = *(const float4*)(qkv + 2 * DD + base);
            }
            k_s[r][c4 + 0] = kv.x; k_s[r][c4 + 1] = kv.y;
            k_s[r][c4 + 2] = kv.z; k_s[r][c4 + 3] = kv.w;
            *(float4*)&v_s[r][c4] = vv;
        }
        __syncthreads();

        int key = t0 + lane;
        bool act = (key <= q);
        float s = -1e30f;
        if (act) {
            float a = 0.f;
#pragma unroll
            for (int d = 0; d < 64; d++) a += qr[d] * k_s[lane][d];
            s = a;
        }
        float mcur = s;
#pragma unroll
        for (int off = 16; off > 0; off >>= 1)
            mcur = fmaxf(mcur, __shfl_xor_sync(0xffffffffu, mcur, off));
        if (mcur > M) {
            float sc = __expf(M - mcur);
            o0 *= sc; o1 *= sc; L *= sc;
            M = mcur;
        }
        float p = act ? __expf(s - M) : 0.f;
        float ls = p;
#pragma unroll
        for (int off = 16; off > 0; off >>= 1)
            ls += __shfl_xor_sync(0xffffffffu, ls, off);
        L += ls;
#pragma unroll
        for (int j = 0; j < 32; j++) {
            float pj = __shfl_sync(0xffffffffu, p, j);
            float2 vv = *(const float2*)&v_s[j][lane * 2];
            o0 += pj * vv.x;
            o1 += pj * vv.y;
        }
    }
    float inv = 1.f / L;
    float2 res; res.x = o0 * inv; res.y = o1 * inv;
    *(float2*)(out + ((size_t)(b * SS + q)) * DD + h * 64 + lane * 2) = res;
}

// ---------------- MoE router ----------------
__global__ void router_kernel(const float* __restrict__ h2, const float* __restrict__ Wg,
                              float* __restrict__ probs, float* __restrict__ topw,
                              int* __restrict__ topi, int* __restrict__ slot_tok,
                              int* __restrict__ tok_slot, int* __restrict__ cnt) {
    int t = blockIdx.x, tid = threadIdx.x;  // 128 threads
    const float* hr = h2 + (size_t)t * DD;
    float a0 = 0, a1 = 0, a2 = 0, a3 = 0;
    for (int d = tid; d < DD; d += 128) {
        float hv = hr[d];
        a0 += hv * Wg[d];
        a1 += hv * Wg[DD + d];
        a2 += hv * Wg[2 * DD + d];
        a3 += hv * Wg[3 * DD + d];
    }
    __shared__ float r[4][128];
    r[0][tid] = a0; r[1][tid] = a1; r[2][tid] = a2; r[3][tid] = a3;
    __syncthreads();
    for (int o = 64; o > 0; o >>= 1) {
        if (tid < o) {
#pragma unroll
            for (int e = 0; e < 4; e++) r[e][tid] += r[e][tid + o];
        }
        __syncthreads();
    }
    if (tid == 0) {
        float l[4] = {r[0][0], r[1][0], r[2][0], r[3][0]};
        float m = fmaxf(fmaxf(l[0], l[1]), fmaxf(l[2], l[3]));
        float p[4], sum = 0.f;
#pragma unroll
        for (int e = 0; e < 4; e++) { p[e] = __expf(l[e] - m); sum += p[e]; }
#pragma unroll
        for (int e = 0; e < 4; e++) { p[e] /= sum; probs[t * 4 + e] = p[e]; }
        int i0 = 0;
#pragma unroll
        for (int e = 1; e < 4; e++) if (p[e] > p[i0]) i0 = e;
        int i1 = -1;
#pragma unroll
        for (int e = 0; e < 4; e++)
            if (e != i0 && (i1 < 0 || p[e] > p[i1])) i1 = e;
        float w0 = p[i0], w1 = p[i1], ws = w0 + w1;
        w0 /= ws; w1 /= ws;
        int pos0 = atomicAdd(&cnt[i0], 1);
        slot_tok[i0 * TT + pos0] = t;
        tok_slot[t * 2]     = i0 * TT + pos0;
        int pos1 = atomicAdd(&cnt[i1], 1);
        slot_tok[i1 * TT + pos1] = t;
        tok_slot[t * 2 + 1] = i1 * TT + pos1;
        topw[t * 2] = w0; topw[t * 2 + 1] = w1;
        topi[t * 2] = i0; topi[t * 2 + 1] = i1;
    }
}

// ---------------- aux loss ----------------
__global__ void aux_kernel(const float* __restrict__ probs, const int* __restrict__ topi,
                           float* __restrict__ auxout) {
    int tid = threadIdx.x;  // 512
    float ps[4] = {0, 0, 0, 0};
    float cs[4] = {0, 0, 0, 0};
    for (int t = tid; t < TT; t += 512) {
#pragma unroll
        for (int e = 0; e < 4; e++) ps[e] += probs[t * 4 + e];
        cs[topi[t * 2]] += 1.f;
        cs[topi[t * 2 + 1]] += 1.f;
    }
    __shared__ float sp[4][512], sc[4][512];
#pragma unroll
    for (int e = 0; e < 4; e++) { sp[e][tid] = ps[e]; sc[e][tid] = cs[e]; }
    __syncthreads();
    for (int o = 256; o > 0; o >>= 1) {
        if (tid < o) {
#pragma unroll
            for (int e = 0; e < 4; e++) {
                sp[e][tid] += sp[e][tid + o];
                sc[e][tid] += sc[e][tid + o];
            }
        }
        __syncthreads();
    }
    if (tid == 0) {
        float aux = 0.f;
#pragma unroll
        for (int e = 0; e < 4; e++) {
            float fi = sc[e][0] / (float)(TT * KSEL);
            float Pi = sp[e][0] / (float)TT;
            aux += fi * Pi;
        }
        auxout[0] = 0.01f * (float)EE * aux;
    }
}

// ---------------- final combine (scalar stores: xout may be 4B-aligned) -------
__global__ void combine_kernel(const float* __restrict__ x1, const float* __restrict__ sdown,
                               const float* __restrict__ eo, const float* __restrict__ topw,
                               const int* __restrict__ tok_slot, float* __restrict__ xout) {
    int t = blockIdx.x, tid = threadIdx.x;
    int c = tid * 4;
    int s0 = tok_slot[t * 2], s1 = tok_slot[t * 2 + 1];
    float w0 = topw[t * 2], w1 = topw[t * 2 + 1];
    float4 a  = *(const float4*)(x1 + (size_t)t * DD + c);
    float4 sd = *(const float4*)(sdown + (size_t)t * DD + c);
    float4 e0 = *(const float4*)(eo + (size_t)s0 * DD + c);
    float4 e1 = *(const float4*)(eo + (size_t)s1 * DD + c);
    float* o = xout + (size_t)t * DD + c;
    o[0] = a.x + sd.x + w0 * e0.x + w1 * e1.x;
    o[1] = a.y + sd.y + w0 * e0.y + w1 * e1.y;
    o[2] = a.z + sd.z + w0 * e0.z + w1 * e1.z;
    o[3] = a.w + sd.w + w0 * e0.w + w1 * e1.w;
}

// ---------------- launch ------------------------------------------------------
extern "C" void kernel_launch(void* const* d_in, const int* in_sizes, int n_in,
                              void* d_out, int out_size) {
    const float* x      = (const float*)d_in[0];
    const float* ln1_g  = (const float*)d_in[1];
    const float* ln1_b  = (const float*)d_in[2];
    const float* Wqkv   = (const float*)d_in[3];
    const float* bqkv   = (const float*)d_in[4];
    const float* Wo     = (const float*)d_in[5];
    const float* bo     = (const float*)d_in[6];
    const float* ln2_g  = (const float*)d_in[7];
    const float* ln2_b  = (const float*)d_in[8];
    const float* Wg     = (const float*)d_in[9];
    const float* We_up  = (const float*)d_in[10];
    const float* be_up  = (const float*)d_in[11];
    const float* We_dn  = (const float*)d_in[12];
    const float* be_dn  = (const float*)d_in[13];
    const float* Ws_up  = (const float*)d_in[14];
    const float* bs_up  = (const float*)d_in[15];
    const float* Ws_dn  = (const float*)d_in[16];
    const float* bs_dn  = (const float*)d_in[17];

    float* F = nullptr; int* I = nullptr;
    cudaGetSymbolAddress((void**)&F, g_f);
    cudaGetSymbolAddress((void**)&I, g_i);

    float* h     = F + OFF_H;
    float* qkv   = F + OFF_QKV;
    float* attn  = F + OFF_ATTN;
    float* x1    = F + OFF_X1;
    float* h2    = F + OFF_H2;
    float* sup   = F + OFF_SUP;
    float* sdown = F + OFF_SDOWN;
    float* upb   = F + OFF_UP;
    float* eob   = F + OFF_EO;
    float* probs = F + OFF_PROBS;
    float* topw  = F + OFF_TOPW;
    int* slot_tok = I + IOFF_SLOT;
    int* tok_slot = I + IOFF_TOKSLOT;
    int* topi     = I + IOFF_TOPI;
    int* cnt      = I + IOFF_CNT;

    float* outp = (float*)d_out;
    float* auxp = nullptr;
    float* xout = outp;
    if (out_size == TT * DD + 1) { auxp = outp; xout = outp + 1; }

    cudaMemsetAsync(cnt, 0, EE * sizeof(int));

    // 1) LN1
    ln_kernel<<<TT, 256>>>(x, ln1_g, ln1_b, h);
    // 2) QKV projection
    hgemm_nt<0><<<dim3(24, 32, 1), 256>>>(h, Wqkv, bqkv, nullptr, qkv,
                                          TT, 3 * DD, DD, nullptr, nullptr, 0, 0, 0, 0, 0);
    // 3) causal attention
    attn_kernel<<<dim3(SS / 16, Bb * HH), 512>>>(qkv, attn);
    // 4) output proj + residual
    hgemm_nt<2><<<dim3(8, 32, 1), 256>>>(attn, Wo, bo, x, x1,
                                         TT, DD, DD, nullptr, nullptr, 0, 0, 0, 0, 0);
    // 5) LN2
    ln_kernel<<<TT, 256>>>(x1, ln2_g, ln2_b, h2);
    // 6) router
    router_kernel<<<TT, 128>>>(h2, Wg, probs, topw, topi, slot_tok, tok_slot, cnt);
    // 7) aux loss
    if (auxp) aux_kernel<<<1, 512>>>(probs, topi, auxp);
    // 8) expert up (gathered, gelu)
    hgemm_nt<1><<<dim3(32, 32, 4), 256>>>(h2, We_up, be_up, nullptr, upb,
                                          TT, HIDD, DD, slot_tok, cnt,
                                          0, (size_t)HIDD * DD, (size_t)HIDD,
                                          (size_t)TT * HIDD, (size_t)TT);
    // 9) expert down
    hgemm_nt<0><<<dim3(8, 32, 4), 256>>>(upb, We_dn, be_dn, nullptr, eob,
                                         TT, DD, HIDD, nullptr, cnt,
                                         (size_t)TT * HIDD, (size_t)DD * HIDD, (size_t)DD,
                                         (size_t)TT * DD, 0);
    // 10) shared expert up (gelu)
    hgemm_nt<1><<<dim3(32, 32, 1), 256>>>(h2, Ws_up, bs_up, nullptr, sup,
                                          TT, HIDD, DD, nullptr, nullptr, 0, 0, 0, 0, 0);
    // 11) shared expert down
    hgemm_nt<0><<<dim3(8, 32, 1), 256>>>(sup, Ws_dn, bs_dn, nullptr, sdown,
                                         TT, DD, HIDD, nullptr, nullptr, 0, 0, 0, 0, 0);
    // 12) combine
    combine_kernel<<<TT, 256>>>(x1, sdown, eob, topw, tok_slot, xout);
}